// round 16
// baseline (speedup 1.0000x reference)
#include <cuda_runtime.h>
#include <cuda_fp16.h>
#include <mma.h>
#include <math.h>

using namespace nvcuda;

#define BD 2
#define TT 2048
#define CC 1024
#define HH 16
#define HD 64

// Scratch (no cudaMalloc allowed)
__device__ __half g_xh[(size_t)BD * TT * CC];
__device__ __half g_wqkvh[(size_t)CC * 3 * CC];      // Q columns pre-scaled by 1/8
__device__ __half g_wprojh[(size_t)CC * CC];
__device__ __half g_qkvh[(size_t)BD * TT * 3 * CC];  // [B,T,3C], q already /8
__device__ __half g_atth[(size_t)BD * TT * CC];
__device__ __half g_eh[(size_t)BD * HH * TT * TT];   // E = exp(S), fp16
__device__ float  g_lp[(size_t)BD * HH * TT * 16];   // per-(row, ktile) partial sums
__device__ float  g_l[(size_t)BD * HH * TT];         // 1/rowsum

typedef wmma::fragment<wmma::matrix_a, 16, 16, 16, __half, wmma::row_major> HA;
typedef wmma::fragment<wmma::matrix_b, 16, 16, 16, __half, wmma::row_major> HBR;
typedef wmma::fragment<wmma::matrix_b, 16, 16, 16, __half, wmma::col_major> HBC;
typedef wmma::fragment<wmma::accumulator, 16, 16, 16, float> HC;

// 0.5*cos(x)+0.5 = 1 + x2*(-1/4 + x2*(1/48 - x2/1440)); |x| small here
__device__ __forceinline__ float cosmask(float x) {
    float x2 = x * x;
    return fmaf(x2, fmaf(x2, fmaf(x2, -6.9444444e-4f, 2.0833333e-2f), -0.25f), 1.0f);
}

__device__ __forceinline__ void cp_async16(void* smem, const void* gmem) {
    unsigned saddr = (unsigned)__cvta_generic_to_shared(smem);
    asm volatile("cp.async.cg.shared.global [%0], [%1], 16;\n" :: "r"(saddr), "l"(gmem));
}
__device__ __forceinline__ void cp_commit() {
    asm volatile("cp.async.commit_group;\n");
}
template <int N>
__device__ __forceinline__ void cp_wait() {
    asm volatile("cp.async.wait_group %0;\n" :: "n"(N));
}

// ---------------------------------------------------------------------------
// fp32 -> fp16 converters
// ---------------------------------------------------------------------------
__global__ void f2h_kernel(__half* __restrict__ dst, const float* __restrict__ src, int n4)
{
    int i = blockIdx.x * 256 + threadIdx.x;
    if (i >= n4) return;
    float4 v = ((const float4*)src)[i];
    ((__half2*)dst)[i * 2 + 0] = __floats2half2_rn(v.x, v.y);
    ((__half2*)dst)[i * 2 + 1] = __floats2half2_rn(v.z, v.w);
}

// Wqkv with Q-columns (col < CC) pre-scaled by 1/8
__global__ void wqkv_cvt_kernel(__half* __restrict__ dst, const float* __restrict__ src)
{
    int i = blockIdx.x * 256 + threadIdx.x;   // n4 = CC*3*CC/4, exact grid
    float4 v = ((const float4*)src)[i];
    int col = (i * 4) % (3 * CC);
    float s = (col < CC) ? 0.125f : 1.f;
    ((__half2*)dst)[i * 2 + 0] = __floats2half2_rn(v.x * s, v.y * s);
    ((__half2*)dst)[i * 2 + 1] = __floats2half2_rn(v.z * s, v.w * s);
}

// ---------------------------------------------------------------------------
// fp16 GEMM, fp32 accum: C[M,N] = A[M,K] @ B[K,N]. BM=BN=128, BK=64,
// 2-stage cp.async double buffer, 8 warps, warp tile 32x64.
// OUTH: half output. MASK: fused learned mask (float output path only).
// ---------------------------------------------------------------------------
#define GALDH 72      // A pad (64+8 halves)
#define GBLDH 136     // B pad (128+8 halves)
#define GA_ST (128 * GALDH)              // 9216 halves
#define GB_ST (64 * GBLDH)               // 8704 halves
#define GST (GA_ST + GB_ST)              // 17920 halves/stage
#define GCLD 132
#define GSMEM_BYTES (2 * GST * 2)        // 71680 >= epi 128*132*4=67584

template <bool OUTH, bool MASK>
__global__ void __launch_bounds__(256, 2) gemm_h(
    const __half* __restrict__ A, const __half* __restrict__ B,
    void* __restrict__ Cout, int M, int N, int K,
    const float* __restrict__ MA, const float* __restrict__ MB)
{
    extern __shared__ __align__(16) unsigned char smraw[];
    __half* smh = (__half*)smraw;
    float* smf = (float*)smraw;

    const int tid = threadIdx.x;
    const int w = tid >> 5;
    const int wm = w & 3;
    const int wn = w >> 2;
    const int bx = blockIdx.x;
    const int by = blockIdx.y;

    const __half* Ab = A + (size_t)by * 128 * K;
    const __half* Bb = B + (size_t)bx * 128;
    const int nK = K >> 6;

    auto loadStage = [&](int s, int kt) {
        __half* As = smh + s * GST;
        __half* Bs = As + GA_ST;
#pragma unroll
        for (int i = 0; i < 4; i++) {
            int idx = tid + i * 256;           // 1024 chunks: A 128x64 halves
            int r = idx >> 3, c8 = (idx & 7) << 3;
            cp_async16(&As[r * GALDH + c8], Ab + (size_t)r * K + kt + c8);
        }
#pragma unroll
        for (int i = 0; i < 4; i++) {
            int idx = tid + i * 256;           // 1024 chunks: B 64x128 halves
            int r = idx >> 4, c8 = (idx & 15) << 3;
            cp_async16(&Bs[r * GBLDH + c8], Bb + (size_t)(kt + r) * N + c8);
        }
        cp_commit();
    };

    HC acc[2][4];
#pragma unroll
    for (int i = 0; i < 2; i++)
#pragma unroll
        for (int j = 0; j < 4; j++) wmma::fill_fragment(acc[i][j], 0.f);

    loadStage(0, 0);

    for (int kt = 0; kt < nK; kt++) {
        cp_wait<0>();
        __syncthreads();
        if (kt + 1 < nK) loadStage((kt + 1) & 1, (kt + 1) << 6);

        __half* As = smh + (kt & 1) * GST;
        __half* Bs = As + GA_ST;
#pragma unroll
        for (int ks = 0; ks < 64; ks += 16) {
            HA af[2];
            HBR bf[4];
#pragma unroll
            for (int i = 0; i < 2; i++)
                wmma::load_matrix_sync(af[i], &As[(wm * 32 + i * 16) * GALDH + ks], GALDH);
#pragma unroll
            for (int j = 0; j < 4; j++)
                wmma::load_matrix_sync(bf[j], &Bs[ks * GBLDH + wn * 64 + j * 16], GBLDH);
#pragma unroll
            for (int i = 0; i < 2; i++)
#pragma unroll
                for (int j = 0; j < 4; j++)
                    wmma::mma_sync(acc[i][j], af[i], bf[j], acc[i][j]);
        }
    }

    __syncthreads();   // pipeline dead; reuse smem as fp32 C staging
#pragma unroll
    for (int i = 0; i < 2; i++)
#pragma unroll
        for (int j = 0; j < 4; j++)
            wmma::store_matrix_sync(&smf[(wm * 32 + i * 16) * GCLD + wn * 64 + j * 16],
                                    acc[i][j], GCLD, wmma::mem_row_major);
    __syncthreads();

    if (OUTH) {
        __half* C = (__half*)Cout;
#pragma unroll
        for (int it = 0; it < 16; it++) {
            int idx = tid + it * 256;
            int r = idx >> 5, c4 = (idx & 31) << 2;
            float4 v = *(const float4*)&smf[r * GCLD + c4];
            __half2 h0 = __floats2half2_rn(v.x, v.y);
            __half2 h1 = __floats2half2_rn(v.z, v.w);
            uint2 u = make_uint2(*(unsigned*)&h0, *(unsigned*)&h1);
            *(uint2*)(C + (size_t)(by * 128 + r) * N + bx * 128 + c4) = u;
        }
    } else {
        float* C = (float*)Cout;
#pragma unroll
        for (int it = 0; it < 16; it++) {
            int idx = tid + it * 256;
            int r = idx >> 5, c4 = (idx & 31) << 2;
            float4 v = *(const float4*)&smf[r * GCLD + c4];
            if (MASK) {
                int col = bx * 128 + c4;
                v.x *= cosmask(fmaf(__ldg(MA + col + 0), v.x, __ldg(MB + col + 0)));
                v.y *= cosmask(fmaf(__ldg(MA + col + 1), v.y, __ldg(MB + col + 1)));
                v.z *= cosmask(fmaf(__ldg(MA + col + 2), v.z, __ldg(MB + col + 2)));
                v.w *= cosmask(fmaf(__ldg(MA + col + 3), v.w, __ldg(MB + col + 3)));
            }
            *(float4*)(C + (size_t)(by * 128 + r) * N + bx * 128 + c4) = v;
        }
    }
}

// ---------------------------------------------------------------------------
// S->E (fp16): one CTA per causal 128x128 tile. grid (136,H,B). (unchanged)
// ---------------------------------------------------------------------------
#define SQLD 72
#define SSLD 132
#define S2E_SMEM (128 * SSLD * 4)

__global__ void __launch_bounds__(256, 2) s2e_h(
    const __half* __restrict__ qkvh, __half* __restrict__ E,
    float* __restrict__ Lp)
{
    extern __shared__ __align__(16) unsigned char smraw[];
    __half* Qs = (__half*)smraw;
    __half* Ks = Qs + 128 * SQLD;
    float* Sbuf = (float*)smraw;

    const int p = blockIdx.x;
    const int h = blockIdx.y;
    const int b = blockIdx.z;
    int qt = 0;
    while ((qt + 1) * (qt + 2) / 2 <= p) qt++;
    const int kt = p - qt * (qt + 1) / 2;

    const int tid = threadIdx.x;
    const int w = tid >> 5;
    const int wm = w & 3;
    const int wn = w >> 2;
    const int lane = tid & 31;
    const size_t bOff = (size_t)b * TT * 3 * CC;
    const int ldq = 3 * CC;
    const int hOff = h * HD;
    const int bh = b * HH + h;
    const size_t eB = ((size_t)bh * TT + (size_t)qt * 128) * TT + (size_t)kt * 128;
    const bool diag = (kt == qt);

#pragma unroll
    for (int i = 0; i < 4; i++) {
        int idx = tid + i * 256;
        int r = idx >> 3, c8 = (idx & 7) << 3;
        *(uint4*)&Qs[r * SQLD + c8] =
            *(const uint4*)(qkvh + bOff + (size_t)(qt * 128 + r) * ldq + hOff + c8);
        *(uint4*)&Ks[r * SQLD + c8] =
            *(const uint4*)(qkvh + bOff + (size_t)(kt * 128 + r) * ldq + CC + hOff + c8);
    }
    __syncthreads();

    HC sacc[2][4];
#pragma unroll
    for (int i = 0; i < 2; i++)
#pragma unroll
        for (int j = 0; j < 4; j++) wmma::fill_fragment(sacc[i][j], 0.f);

#pragma unroll
    for (int ks = 0; ks < 64; ks += 16) {
        HA af[2];
        HBC bf[4];
#pragma unroll
        for (int i = 0; i < 2; i++)
            wmma::load_matrix_sync(af[i], &Qs[(wm * 32 + i * 16) * SQLD + ks], SQLD);
#pragma unroll
        for (int j = 0; j < 4; j++)
            wmma::load_matrix_sync(bf[j], &Ks[(wn * 64 + j * 16) * SQLD + ks], SQLD);
#pragma unroll
        for (int i = 0; i < 2; i++)
#pragma unroll
            for (int j = 0; j < 4; j++)
                wmma::mma_sync(sacc[i][j], af[i], bf[j], sacc[i][j]);
    }

    __syncthreads();   // Qs/Ks dead; Sbuf may overwrite
#pragma unroll
    for (int i = 0; i < 2; i++)
#pragma unroll
        for (int j = 0; j < 4; j++)
            wmma::store_matrix_sync(&Sbuf[(wm * 32 + i * 16) * SSLD + wn * 64 + j * 16],
                                    sacc[i][j], SSLD, wmma::mem_row_major);
    __syncthreads();

    // exp + (diag causal zero) + E(half) write + per-row warp sums -> Lp
#pragma unroll
    for (int i = 0; i < 16; i++) {
        int r = w + i * 8;
        int c = lane << 2;
        float4 s4 = *(const float4*)&Sbuf[r * SSLD + c];
        float4 e4;
        if (diag) {
            e4.x = (c + 0 <= r) ? __expf(fminf(s4.x, 60.f)) : 0.f;
            e4.y = (c + 1 <= r) ? __expf(fminf(s4.y, 60.f)) : 0.f;
            e4.z = (c + 2 <= r) ? __expf(fminf(s4.z, 60.f)) : 0.f;
            e4.w = (c + 3 <= r) ? __expf(fminf(s4.w, 60.f)) : 0.f;
        } else {
            e4.x = __expf(fminf(s4.x, 60.f));
            e4.y = __expf(fminf(s4.y, 60.f));
            e4.z = __expf(fminf(s4.z, 60.f));
            e4.w = __expf(fminf(s4.w, 60.f));
        }
        __half2 h0 = __floats2half2_rn(e4.x, e4.y);
        __half2 h1 = __floats2half2_rn(e4.z, e4.w);
        uint2 u = make_uint2(*(unsigned*)&h0, *(unsigned*)&h1);
        *(uint2*)(E + eB + (size_t)r * TT + c) = u;

        float s = (e4.x + e4.y) + (e4.z + e4.w);
#pragma unroll
        for (int o = 16; o > 0; o >>= 1) s += __shfl_xor_sync(0xffffffffu, s, o);
        if (lane == 0)
            Lp[((size_t)bh * TT + qt * 128 + r) * 16 + kt] = s;
    }
}

// ---------------------------------------------------------------------------
// Reciprocal of row sums. (unchanged)
// ---------------------------------------------------------------------------
__global__ void recip_kernel(const float* __restrict__ Lp, float* __restrict__ L, int n)
{
    int i = blockIdx.x * 256 + threadIdx.x;
    if (i >= n) return;
    int r = i & (TT - 1);
    int nk = (r >> 7) + 1;
    const float* p = Lp + (size_t)i * 16;
    float s = 0.f;
    for (int k = 0; k < nk; k++) s += p[k];
    L[i] = 1.f / s;
}

// ---------------------------------------------------------------------------
// PV (fp16): per (qt,h,b) CTA. O[128x64] = sum_kt P'(128x128) V(128x64).
// V double-buffered via cp.async (prefetch kt+1 during MMA of kt).
// Smem: Ps 128x136 half (34.8KB, reused fp32 Obuf) + Vs[2] 128x72 half
// (36.9KB) + ls (0.5KB) = 72.2KB, 2 CTAs/SM.
// ---------------------------------------------------------------------------
#define PLD 136
#define PVLD 72
#define PV_PS_BYTE (128 * PLD * 2)                     // 34816
#define PV_V_BYTE (128 * PVLD * 2)                     // 18432 per buffer
#define PV_LS_OFF (PV_PS_BYTE + 2 * PV_V_BYTE)         // 71680
#define PV_SMEM (PV_LS_OFF + 128 * 4)                  // 72192

__global__ void __launch_bounds__(256, 2) pv_h(
    const __half* __restrict__ qkvh, const __half* __restrict__ E,
    const float* __restrict__ L,
    const float* __restrict__ A1, const float* __restrict__ B1,
    __half* __restrict__ atth)
{
    extern __shared__ __align__(16) unsigned char smraw[];
    __half* Ps = (__half*)smraw;
    __half* Vs0 = (__half*)(smraw + PV_PS_BYTE);
    float* ls = (float*)(smraw + PV_LS_OFF);
    float* Obuf = (float*)smraw;       // reused after mainloop (128x68 fp32)

    const int tid = threadIdx.x;
    const int w = tid >> 5;
    const int wm = w & 3;
    const int wn = w >> 2;
    const int qt = (gridDim.x - 1) - blockIdx.x;   // heavy first
    const int h = blockIdx.y;
    const int b = blockIdx.z;
    const int bh = b * HH + h;
    const size_t bOff = (size_t)b * TT * 3 * CC;
    const int ldq = 3 * CC;
    const int hOff = h * HD;
    const size_t eQ = ((size_t)bh * TT + (size_t)qt * 128) * TT;

    auto loadV = [&](int buf, int kBase) {
        __half* Vd = Vs0 + buf * (PV_V_BYTE / 2);
#pragma unroll
        for (int i = 0; i < 4; i++) {
            int idx = tid + i * 256;
            int r = idx >> 3, c8 = (idx & 7) << 3;
            cp_async16(&Vd[r * PVLD + c8],
                       qkvh + bOff + (size_t)(kBase + r) * ldq + 2 * CC + hOff + c8);
        }
        cp_commit();
    };

    if (tid < 128) ls[tid] = L[bh * TT + qt * 128 + tid];
    loadV(0, 0);

    HC oacc[2][2];
#pragma unroll
    for (int i = 0; i < 2; i++)
#pragma unroll
        for (int t = 0; t < 2; t++) wmma::fill_fragment(oacc[i][t], 0.f);

    __syncthreads();   // ls visible

    for (int kt = 0; kt <= qt; kt++) {
        const int kBase = kt * 128;
        // E(half) -> P' (half staged); overlaps in-flight V(kt) cp.async
#pragma unroll
        for (int i = 0; i < 16; i++) {
            int r = w + i * 8;
            int c = (tid & 31) << 2;
            uint2 ue = *(const uint2*)(E + eQ + (size_t)r * TT + kBase + c);
            float2 f0 = __half22float2(*(__half2*)&ue.x);
            float2 f1 = __half22float2(*(__half2*)&ue.y);
            float rl = ls[r];
            int k0 = kBase + c;
            float4 p4;
            p4.x = f0.x * rl; p4.y = f0.y * rl;
            p4.z = f1.x * rl; p4.w = f1.y * rl;
            p4.x *= cosmask(fmaf(__ldg(A1 + k0 + 0), p4.x, __ldg(B1 + k0 + 0)));
            p4.y *= cosmask(fmaf(__ldg(A1 + k0 + 1), p4.y, __ldg(B1 + k0 + 1)));
            p4.z *= cosmask(fmaf(__ldg(A1 + k0 + 2), p4.z, __ldg(B1 + k0 + 2)));
            p4.w *= cosmask(fmaf(__ldg(A1 + k0 + 3), p4.w, __ldg(B1 + k0 + 3)));
            __half2 h0 = __floats2half2_rn(p4.x, p4.y);
            __half2 h1 = __floats2half2_rn(p4.z, p4.w);
            uint2 u = make_uint2(*(unsigned*)&h0, *(unsigned*)&h1);
            *(uint2*)&Ps[r * PLD + c] = u;
        }
        cp_wait<0>();      // V(kt) landed
        __syncthreads();   // Ps + Vs[kt&1] ready for all warps
        if (kt < qt) loadV((kt + 1) & 1, kBase + 128);   // prefetch V(kt+1)

        __half* Vc = Vs0 + (kt & 1) * (PV_V_BYTE / 2);
#pragma unroll
        for (int ks = 0; ks < 128; ks += 16) {
            HA af[2];
#pragma unroll
            for (int i = 0; i < 2; i++)
                wmma::load_matrix_sync(af[i], &Ps[(wm * 32 + i * 16) * PLD + ks], PLD);
#pragma unroll
            for (int t = 0; t < 2; t++) {
                HBR bf;
                wmma::load_matrix_sync(bf, &Vc[ks * PVLD + wn * 32 + t * 16], PVLD);
#pragma unroll
                for (int i = 0; i < 2; i++)
                    wmma::mma_sync(oacc[i][t], af[i], bf, oacc[i][t]);
            }
        }
        __syncthreads();   // MMA done before next transform overwrites Ps
    }

    // epilogue: stage fp32 O, convert to half att
#pragma unroll
    for (int i = 0; i < 2; i++)
#pragma unroll
        for (int t = 0; t < 2; t++)
            wmma::store_matrix_sync(&Obuf[(wm * 32 + i * 16) * 68 + wn * 32 + t * 16],
                                    oacc[i][t], 68, wmma::mem_row_major);
    __syncthreads();

    const size_t oBase = (size_t)b * TT * CC + (size_t)qt * 128 * CC + hOff;
#pragma unroll
    for (int it = 0; it < 8; it++) {
        int idx = tid + it * 256;
        int r = idx >> 4, c4 = (idx & 15) << 2;
        float4 v = *(const float4*)&Obuf[r * 68 + c4];
        __half2 h0 = __floats2half2_rn(v.x, v.y);
        __half2 h1 = __floats2half2_rn(v.z, v.w);
        uint2 u = make_uint2(*(unsigned*)&h0, *(unsigned*)&h1);
        *(uint2*)(atth + oBase + (size_t)r * CC + c4) = u;
    }
}

// ---------------------------------------------------------------------------
extern "C" void kernel_launch(void* const* d_in, const int* in_sizes, int n_in,
                              void* d_out, int out_size)
{
    const float* x     = (const float*)d_in[0];
    const float* Wqkv  = (const float*)d_in[1];
    const float* Wproj = (const float*)d_in[2];
    const float* A1    = (const float*)d_in[3];
    const float* B1    = (const float*)d_in[4];
    const float* A2    = (const float*)d_in[5];
    const float* B2    = (const float*)d_in[6];
    float* out = (float*)d_out;

    __half *xh, *wqkvh, *wprojh, *qkvh, *atth, *E;
    float *Lp, *L;
    cudaGetSymbolAddress((void**)&xh, g_xh);
    cudaGetSymbolAddress((void**)&wqkvh, g_wqkvh);
    cudaGetSymbolAddress((void**)&wprojh, g_wprojh);
    cudaGetSymbolAddress((void**)&qkvh, g_qkvh);
    cudaGetSymbolAddress((void**)&atth, g_atth);
    cudaGetSymbolAddress((void**)&E, g_eh);
    cudaGetSymbolAddress((void**)&Lp, g_lp);
    cudaGetSymbolAddress((void**)&L, g_l);

    cudaFuncSetAttribute((const void*)gemm_h<true, false>,
                         cudaFuncAttributeMaxDynamicSharedMemorySize, GSMEM_BYTES);
    cudaFuncSetAttribute((const void*)gemm_h<false, true>,
                         cudaFuncAttributeMaxDynamicSharedMemorySize, GSMEM_BYTES);
    cudaFuncSetAttribute((const void*)s2e_h,
                         cudaFuncAttributeMaxDynamicSharedMemorySize, S2E_SMEM);
    cudaFuncSetAttribute((const void*)pv_h,
                         cudaFuncAttributeMaxDynamicSharedMemorySize, PV_SMEM);

    // 0) convert inputs to fp16 (Wqkv with Q-scale folded)
    f2h_kernel<<<(BD * TT * CC / 4 + 255) / 256, 256>>>(xh, x, BD * TT * CC / 4);
    wqkv_cvt_kernel<<<(CC * 3 * CC / 4) / 256, 256>>>(wqkvh, Wqkv);
    f2h_kernel<<<(CC * CC / 4 + 255) / 256, 256>>>(wprojh, Wproj, CC * CC / 4);

    // 1) QKV projection (half out): [4096,1024] @ [1024,3072]
    {
        dim3 grid(3 * CC / 128, (BD * TT) / 128);
        gemm_h<true, false><<<grid, 256, GSMEM_BYTES>>>(
            xh, wqkvh, qkvh, BD * TT, 3 * CC, CC, nullptr, nullptr);
    }
    // 2a) S -> E (half) + partial row sums
    {
        dim3 grid(136, HH, BD);
        s2e_h<<<grid, 256, S2E_SMEM>>>(qkvh, E, Lp);
    }
    // 2b) combine partials -> 1/l
    recip_kernel<<<(BD * HH * TT + 255) / 256, 256>>>(Lp, L, BD * HH * TT);
    // 2c) O = P' V (half out)
    {
        dim3 grid(TT / 128, HH, BD);
        pv_h<<<grid, 256, PV_SMEM>>>(qkvh, E, L, A1, B1, atth);
    }
    // 3) output projection + fused learned mask (float out)
    {
        dim3 grid(CC / 128, (BD * TT) / 128);
        gemm_h<false, true><<<grid, 256, GSMEM_BYTES>>>(
            atth, wprojh, out, BD * TT, CC, CC, A2, B2);
    }
}